// round 4
// baseline (speedup 1.0000x reference)
#include <cuda_runtime.h>
#include <cuda_bf16.h>

#define NRAYS 4096
#define NTETS 3072
#define NFACE 12288
#define MAXS  128

// ---------------- scratch (device globals; no allocations) ------------------
__device__ float4 g_btri[NFACE * 3];   // boundary tri: p0,e1,e2; fid in [0].w
__device__ int    g_nb;                // boundary tri count

struct F3 { float x, y, z; };
__device__ __forceinline__ F3 mkf3(float x, float y, float z) { F3 r; r.x = x; r.y = y; r.z = z; return r; }
__device__ __forceinline__ F3 sub3(F3 a, F3 b) { return mkf3(a.x - b.x, a.y - b.y, a.z - b.z); }
__device__ __forceinline__ F3 cross3(F3 a, F3 b) {
    return mkf3(a.y * b.z - a.z * b.y,
                a.z * b.x - a.x * b.z,
                a.x * b.y - a.y * b.x);
}
__device__ __forceinline__ float dot3(F3 a, F3 b) { return a.x * b.x + a.y * b.y + a.z * b.z; }
__device__ __forceinline__ F3 ld3(const float* p) { return mkf3(p[0], p[1], p[2]); }

// ---------------- kernel A: single block — reset + compact boundary tris ----
// topo flattened (NTETS*4) is indexed exactly by face id; boundary <=> topo<0.
// First hit of a ray from outside a watertight mesh is always a boundary face.
__global__ void k_prep(const float* __restrict__ verts,
                       const int* __restrict__ faces,
                       const int* __restrict__ topo) {
    if (threadIdx.x == 0) g_nb = 0;
    __syncthreads();
    for (int fid = threadIdx.x; fid < NFACE; fid += blockDim.x) {
        if (topo[fid] >= 0) continue;
        int slot = atomicAdd(&g_nb, 1);
        int v0 = faces[3 * fid + 0];
        int v1 = faces[3 * fid + 1];
        int v2 = faces[3 * fid + 2];
        F3 p0 = ld3(verts + 3 * v0);
        F3 p1 = ld3(verts + 3 * v1);
        F3 p2 = ld3(verts + 3 * v2);
        g_btri[3 * slot + 0] = make_float4(p0.x, p0.y, p0.z, __int_as_float(fid));
        g_btri[3 * slot + 1] = make_float4(p1.x - p0.x, p1.y - p0.y, p1.z - p0.z, 0.0f);
        g_btri[3 * slot + 2] = make_float4(p2.x - p0.x, p2.y - p0.y, p2.z - p0.z, 0.0f);
    }
}

// ---------------- kernel B: fused intersect + march --------------------------
// Block = 256 threads = 32 rays x 8 tri-slices.
// Phase 1: Moller-Trumbore over boundary tris, 8-way split per ray, reduced
//          via shared atomicMin on packed (t_bits<<32 | fid).
// Phase 2: warp 0 marches its 32 rays (R3's exact bary arithmetic with
//          register-cached tet data); results staged in shared memory in
//          32-step chunks and flushed to global coalesced by all 8 warps.
__global__ void __launch_bounds__(256) k_fused(const float* __restrict__ verts,
                                               const float* __restrict__ ro,
                                               const float* __restrict__ rd,
                                               const int* __restrict__ tetras,
                                               const int* __restrict__ topo,
                                               float* __restrict__ out) {
    __shared__ unsigned long long skey[32];
    __shared__ float sray[32][33], stet[32][33];
    __shared__ float sb0[32][33], sb1[32][33], sb2[32][33], sb3[32][33];
    __shared__ float spx[32][33], spy[32][33], spz[32][33];

    int tid  = threadIdx.x;
    int lane = tid & 31;
    int wid  = tid >> 5;
    int ray  = blockIdx.x * 32 + lane;

    F3 o = ld3(ro + 3 * ray);
    F3 d = ld3(rd + 3 * ray);

    if (tid < 32)
        skey[tid] = ((unsigned long long)__float_as_uint(1e10f) << 32); // (1e10, 0)
    __syncthreads();

    // ---------------- phase 1: intersect (slice = wid, stride 8) ------------
    {
        int nb = g_nb;
        float tmin = 1e10f;
        int   fmin = 0x7fffffff;
        for (int s = wid; s < nb; s += 8) {
            float4 q0 = g_btri[3 * s + 0];
            float4 q1 = g_btri[3 * s + 1];
            float4 q2 = g_btri[3 * s + 2];
            F3 p0 = mkf3(q0.x, q0.y, q0.z);
            F3 e1 = mkf3(q1.x, q1.y, q1.z);
            F3 e2 = mkf3(q2.x, q2.y, q2.z);
            int fid = __float_as_int(q0.w);

            F3 h = cross3(d, e2);
            float a = dot3(e1, h);
            bool anz = fabsf(a) > 1e-9f;
            float f = 1.0f / (anz ? a : 1e-9f);
            F3 s3 = sub3(o, p0);
            float u = f * dot3(s3, h);
            F3 q = cross3(s3, e1);
            float v = f * dot3(d, q);
            float tt = f * dot3(e2, q);
            bool ok = anz && (u >= 0.0f) && (u <= 1.0f) && (v >= 0.0f) &&
                      (u + v <= 1.0f) && (tt > 1e-6f);
            if (ok && (tt < tmin || (tt == tmin && fid < fmin))) { tmin = tt; fmin = fid; }
        }
        if (tmin < 1e10f) {
            unsigned long long key =
                ((unsigned long long)__float_as_uint(tmin) << 32) | (unsigned)fmin;
            atomicMin(&skey[lane], key);
        }
    }
    __syncthreads();

    // ---------------- phase 2: march (warp 0) + cooperative flush ------------
    float* o_ray = out;
    float* o_tet = out + (size_t)NRAYS * MAXS;
    float* o_bar = out + (size_t)2 * NRAYS * MAXS;
    float* o_ts  = out + (size_t)6 * NRAYS * MAXS;
    float* o_te  = o_ts + NRAYS;
    float* o_pos = o_te + NRAYS;

    // per-lane march state (meaningful only in warp 0)
    F3 hp = mkf3(0.f, 0.f, 0.f);
    int  tet = 0;
    bool alive = false;
    F3 ca, ce1, ce2, ce3, cc23;
    float cinv = 0.0f;

    if (wid == 0) {
        unsigned long long key = skey[lane];
        float tmin = __uint_as_float((unsigned)(key >> 32));
        int   fidx = (int)(key & 0xffffffffu);
        bool  hit = tmin < 5.0f;
        float t0  = hit ? tmin : 0.0f;
        hp = mkf3(o.x + t0 * d.x, o.y + t0 * d.y, o.z + t0 * d.z);
        tet   = hit ? (fidx >> 2) : 0;
        alive = hit;

        o_ts[ray] = t0;                          // lanes -> consecutive rays: coalesced
        o_te[ray] = hit ? (t0 + 0.05f) : 0.0f;

        if (alive) {                             // identical arithmetic to R3
            int4 tv = ((const int4*)tetras)[tet];
            ca  = ld3(verts + 3 * tv.x);
            F3 b  = ld3(verts + 3 * tv.y);
            F3 c  = ld3(verts + 3 * tv.z);
            F3 dd = ld3(verts + 3 * tv.w);
            ce1 = sub3(b, ca);
            ce2 = sub3(c, ca);
            ce3 = sub3(dd, ca);
            cc23 = cross3(ce2, ce3);
            float det = dot3(ce1, cc23);
            cinv = 1.0f / det;
        }
    }

    const float STEPF = (float)(0.05 / 128.0);

    for (int chunk = 0; chunk < 4; ++chunk) {
        if (wid == 0) {
            for (int kk = 0; kk < 32; ++kk) {
                int k = chunk * 32 + kk;
                float w0 = 0.f, w1 = 0.f, w2 = 0.f, w3 = 0.f;
                F3 p = mkf3(0.f, 0.f, 0.f);
                bool valid = false;

                if (alive) {
                    float tk = (float)k * STEPF + 1e-4f;
                    p = mkf3(hp.x + tk * d.x, hp.y + tk * d.y, hp.z + tk * d.z);

                    bool inside = false;
                    bool moved_last = false;
                    for (int it = 0; it < 3; ++it) {
                        F3 r = sub3(p, ca);
                        w1 = dot3(r, cc23) * cinv;
                        F3 cr3 = cross3(r, ce3);
                        w2 = dot3(ce1, cr3) * cinv;
                        F3 c2r = cross3(ce2, r);
                        w3 = dot3(ce1, c2r) * cinv;
                        w0 = 1.0f - (w1 + w2 + w3);
                        inside = (w0 >= -1e-6f) && (w1 >= -1e-6f) &&
                                 (w2 >= -1e-6f) && (w3 >= -1e-6f);
                        moved_last = false;
                        if (inside) break;
                        int am = 0; float mv = w0;
                        if (w1 < mv) { mv = w1; am = 1; }
                        if (w2 < mv) { mv = w2; am = 2; }
                        if (w3 < mv) { mv = w3; am = 3; }
                        int nb = topo[4 * tet + (3 - am)];
                        if (nb >= 0) {
                            tet = nb;
                            int4 tv = ((const int4*)tetras)[tet];
                            ca  = ld3(verts + 3 * tv.x);
                            F3 b  = ld3(verts + 3 * tv.y);
                            F3 c  = ld3(verts + 3 * tv.z);
                            F3 dd = ld3(verts + 3 * tv.w);
                            ce1 = sub3(b, ca);
                            ce2 = sub3(c, ca);
                            ce3 = sub3(dd, ca);
                            cc23 = cross3(ce2, ce3);
                            float det = dot3(ce1, cc23);
                            cinv = 1.0f / det;
                            moved_last = true;
                        } else { alive = false; break; }
                    }
                    if (alive && !inside && moved_last) {
                        F3 r = sub3(p, ca);
                        w1 = dot3(r, cc23) * cinv;
                        F3 cr3 = cross3(r, ce3);
                        w2 = dot3(ce1, cr3) * cinv;
                        F3 c2r = cross3(ce2, r);
                        w3 = dot3(ce1, c2r) * cinv;
                        w0 = 1.0f - (w1 + w2 + w3);
                        inside = (w0 >= -1e-6f) && (w1 >= -1e-6f) &&
                                 (w2 >= -1e-6f) && (w3 >= -1e-6f);
                    }
                    valid = alive && inside;
                }

                if (valid) {
                    sray[lane][kk] = (float)ray;
                    stet[lane][kk] = (float)tet;
                    sb0[lane][kk] = w0; sb1[lane][kk] = w1;
                    sb2[lane][kk] = w2; sb3[lane][kk] = w3;
                    spx[lane][kk] = p.x; spy[lane][kk] = p.y; spz[lane][kk] = p.z;
                } else {
                    sray[lane][kk] = -1.0f;
                    stet[lane][kk] = -1.0f;
                    sb0[lane][kk] = 0.f; sb1[lane][kk] = 0.f;
                    sb2[lane][kk] = 0.f; sb3[lane][kk] = 0.f;
                    spx[lane][kk] = 0.f; spy[lane][kk] = 0.f; spz[lane][kk] = 0.f;
                }
            }
        }
        __syncthreads();

        // cooperative coalesced flush: 32 rays x 32 steps, lanes cover k
        int base = chunk * 32;
#pragma unroll
        for (int i = 0; i < 4; ++i) {
            int id = tid + i * 256;          // 0..1023
            int r  = id >> 5;
            int kk = id & 31;
            int idx = (blockIdx.x * 32 + r) * MAXS + base + kk;
            o_ray[idx] = sray[r][kk];
            o_tet[idx] = stet[r][kk];
            ((float4*)o_bar)[idx] =
                make_float4(sb0[r][kk], sb1[r][kk], sb2[r][kk], sb3[r][kk]);
            o_pos[3 * idx + 0] = spx[r][kk];
            o_pos[3 * idx + 1] = spy[r][kk];
            o_pos[3 * idx + 2] = spz[r][kk];
        }
        __syncthreads();
    }
}

// ---------------- launch ------------------------------------------------------
extern "C" void kernel_launch(void* const* d_in, const int* in_sizes, int n_in,
                              void* d_out, int out_size) {
    const float* cage   = (const float*)d_in[0];  // (1, 729, 3) f32
    const float* ro     = (const float*)d_in[1];  // (1, 4096, 3) f32
    const float* rd     = (const float*)d_in[2];  // (1, 4096, 3) f32
    const int*   tetras = (const int*)d_in[3];    // (3072, 4) i32
    const int*   faces  = (const int*)d_in[4];    // (3072, 4, 3) i32
    const int*   topo   = (const int*)d_in[5];    // (3072, 4) i32
    float* out = (float*)d_out;

    k_prep<<<1, 256>>>(cage, faces, topo);
    k_fused<<<NRAYS / 32, 256>>>(cage, ro, rd, tetras, topo, out);
}

// round 5
// speedup vs baseline: 1.0203x; 1.0203x over previous
#include <cuda_runtime.h>
#include <cuda_bf16.h>

#define NRAYS 4096
#define NTETS 3072
#define NFACE 12288
#define MAXS  128

// ---------------- scratch (device globals; no allocations) ------------------
__device__ float4 g_btri[NFACE * 3];            // boundary tri: p0,e1,e2; fid in [0].w
__device__ int    g_nb;                          // boundary tri count
__device__ unsigned long long g_key[NRAYS];      // packed (t_bits<<32 | face_idx)

struct F3 { float x, y, z; };
__device__ __forceinline__ F3 mkf3(float x, float y, float z) { F3 r; r.x = x; r.y = y; r.z = z; return r; }
__device__ __forceinline__ F3 sub3(F3 a, F3 b) { return mkf3(a.x - b.x, a.y - b.y, a.z - b.z); }
__device__ __forceinline__ F3 cross3(F3 a, F3 b) {
    return mkf3(a.y * b.z - a.z * b.y,
                a.z * b.x - a.x * b.z,
                a.x * b.y - a.y * b.x);
}
__device__ __forceinline__ float dot3(F3 a, F3 b) { return a.x * b.x + a.y * b.y + a.z * b.z; }
__device__ __forceinline__ F3 ld3(const float* p) { return mkf3(p[0], p[1], p[2]); }

// ---------------- kernel A: single block — compact boundary tris -------------
// topo flattened (NTETS*4) is indexed exactly by face id; boundary <=> topo<0.
// First hit of a ray from outside a watertight mesh is always a boundary face.
__global__ void k_prep(const float* __restrict__ verts,
                       const int* __restrict__ faces,
                       const int* __restrict__ topo) {
    if (threadIdx.x == 0) g_nb = 0;
    __syncthreads();
    for (int fid = threadIdx.x; fid < NFACE; fid += blockDim.x) {
        if (topo[fid] >= 0) continue;
        int slot = atomicAdd(&g_nb, 1);
        int v0 = faces[3 * fid + 0];
        int v1 = faces[3 * fid + 1];
        int v2 = faces[3 * fid + 2];
        F3 p0 = ld3(verts + 3 * v0);
        F3 p1 = ld3(verts + 3 * v1);
        F3 p2 = ld3(verts + 3 * v2);
        g_btri[3 * slot + 0] = make_float4(p0.x, p0.y, p0.z, __int_as_float(fid));
        g_btri[3 * slot + 1] = make_float4(p1.x - p0.x, p1.y - p0.y, p1.z - p0.z, 0.0f);
        g_btri[3 * slot + 2] = make_float4(p2.x - p0.x, p2.y - p0.y, p2.z - p0.z, 0.0f);
    }
}

// ---------------- kernel B: intersect, block-reduced -------------------------
// Block = 256 threads = 32 rays x 8 tri-slices; shared atomicMin on packed
// (t_bits<<32 | fid) reproduces first-occurrence argmin; one coalesced g_key
// write per block. No global init pass needed.
__global__ void __launch_bounds__(256) k_isect(const float* __restrict__ ro,
                                               const float* __restrict__ rd) {
    __shared__ unsigned long long skey[32];
    int tid  = threadIdx.x;
    int lane = tid & 31;
    int wid  = tid >> 5;
    int ray  = blockIdx.x * 32 + lane;

    if (tid < 32)
        skey[tid] = ((unsigned long long)__float_as_uint(1e10f) << 32); // (1e10, 0)
    __syncthreads();

    F3 o = ld3(ro + 3 * ray);
    F3 d = ld3(rd + 3 * ray);
    int nb = g_nb;

    float tmin = 1e10f;
    int   fmin = 0x7fffffff;
    for (int s = wid; s < nb; s += 8) {
        float4 q0 = g_btri[3 * s + 0];
        float4 q1 = g_btri[3 * s + 1];
        float4 q2 = g_btri[3 * s + 2];
        F3 p0 = mkf3(q0.x, q0.y, q0.z);
        F3 e1 = mkf3(q1.x, q1.y, q1.z);
        F3 e2 = mkf3(q2.x, q2.y, q2.z);
        int fid = __float_as_int(q0.w);

        F3 h = cross3(d, e2);
        float a = dot3(e1, h);
        bool anz = fabsf(a) > 1e-9f;
        float f = 1.0f / (anz ? a : 1e-9f);
        F3 s3 = sub3(o, p0);
        float u = f * dot3(s3, h);
        F3 q = cross3(s3, e1);
        float v = f * dot3(d, q);
        float tt = f * dot3(e2, q);
        bool ok = anz && (u >= 0.0f) && (u <= 1.0f) && (v >= 0.0f) &&
                  (u + v <= 1.0f) && (tt > 1e-6f);
        if (ok && (tt < tmin || (tt == tmin && fid < fmin))) { tmin = tt; fmin = fid; }
    }
    if (tmin < 1e10f) {
        unsigned long long key =
            ((unsigned long long)__float_as_uint(tmin) << 32) | (unsigned)fmin;
        atomicMin(&skey[lane], key);
    }
    __syncthreads();
    if (tid < 32) g_key[ray] = skey[tid];
}

// ---------------- kernel C: march with 4-wide speculative batching -----------
// Common case: sample is inside the carried tet at the first bary (reference's
// it=0 path). Compute 4 consecutive samples' bary against the cached tet as
// independent chains; any failure falls into the verbatim R3 walk and restarts
// the batch with the new tet. All arithmetic is op-identical to R3.
__global__ void __launch_bounds__(32) k_march(const float* __restrict__ verts,
                                              const float* __restrict__ ro,
                                              const float* __restrict__ rd,
                                              const int* __restrict__ tetras,
                                              const int* __restrict__ topo,
                                              float* __restrict__ out) {
    int ray = blockIdx.x * 32 + threadIdx.x;

    unsigned long long key = g_key[ray];
    float tmin = __uint_as_float((unsigned)(key >> 32));
    int   fidx = (int)(key & 0xffffffffu);

    bool  hit = tmin < 5.0f;
    float t0  = hit ? tmin : 0.0f;
    F3 o = ld3(ro + 3 * ray);
    F3 d = ld3(rd + 3 * ray);
    F3 hp = mkf3(o.x + t0 * d.x, o.y + t0 * d.y, o.z + t0 * d.z);
    int  tet   = hit ? (fidx >> 2) : 0;
    bool alive = hit;

    float* o_ray = out;
    float* o_tet = out + (size_t)NRAYS * MAXS;
    float* o_bar = out + (size_t)2 * NRAYS * MAXS;
    float* o_ts  = out + (size_t)6 * NRAYS * MAXS;
    float* o_te  = o_ts + NRAYS;
    float* o_pos = o_te + NRAYS;

    o_ts[ray] = t0;
    o_te[ray] = hit ? (t0 + 0.05f) : 0.0f;

    const float STEPF = (float)(0.05 / 128.0);

    // register-cached tet data (identical computation to R3)
    F3 ca, ce1, ce2, ce3, cc23;
    float cinv = 0.0f;
    if (alive) {
        int4 tv = ((const int4*)tetras)[tet];
        ca  = ld3(verts + 3 * tv.x);
        F3 b  = ld3(verts + 3 * tv.y);
        F3 c  = ld3(verts + 3 * tv.z);
        F3 dd = ld3(verts + 3 * tv.w);
        ce1 = sub3(b, ca);
        ce2 = sub3(c, ca);
        ce3 = sub3(dd, ca);
        cc23 = cross3(ce2, ce3);
        float det = dot3(ce1, cc23);
        cinv = 1.0f / det;
    }

    int k = 0;
    while (alive && k < MAXS) {
        int kb = MAXS - k;
        if (kb > 4) kb = 4;

        float W0[4], W1[4], W2[4], W3[4], PXa[4], PYa[4], PZa[4];
#pragma unroll
        for (int j = 0; j < 4; ++j) {
            if (j < kb) {
                float tk = (float)(k + j) * STEPF + 1e-4f;
                F3 p = mkf3(hp.x + tk * d.x, hp.y + tk * d.y, hp.z + tk * d.z);
                F3 r = sub3(p, ca);
                float w1 = dot3(r, cc23) * cinv;
                F3 cr3 = cross3(r, ce3);
                float w2 = dot3(ce1, cr3) * cinv;
                F3 c2r = cross3(ce2, r);
                float w3 = dot3(ce1, c2r) * cinv;
                W1[j] = w1; W2[j] = w2; W3[j] = w3;
                W0[j] = 1.0f - (w1 + w2 + w3);
                PXa[j] = p.x; PYa[j] = p.y; PZa[j] = p.z;
            }
        }

        int j = 0;
        bool restart = false;
        for (; j < kb; ++j) {
            float w0 = W0[j], w1 = W1[j], w2 = W2[j], w3 = W3[j];
            F3 p = mkf3(PXa[j], PYa[j], PZa[j]);
            bool inside = (w0 >= -1e-6f) && (w1 >= -1e-6f) &&
                          (w2 >= -1e-6f) && (w3 >= -1e-6f);
            bool valid;
            if (inside) {
                valid = true;
            } else {
                // slow path: verbatim R3 walk, it=0 bary already in w*
                restart = true;
                bool moved_last = false;
                for (int it = 0; it < 3; ++it) {
                    if (it > 0) {
                        F3 r = sub3(p, ca);
                        w1 = dot3(r, cc23) * cinv;
                        F3 cr3 = cross3(r, ce3);
                        w2 = dot3(ce1, cr3) * cinv;
                        F3 c2r = cross3(ce2, r);
                        w3 = dot3(ce1, c2r) * cinv;
                        w0 = 1.0f - (w1 + w2 + w3);
                        inside = (w0 >= -1e-6f) && (w1 >= -1e-6f) &&
                                 (w2 >= -1e-6f) && (w3 >= -1e-6f);
                    }
                    moved_last = false;
                    if (inside) break;
                    int am = 0; float mv = w0;
                    if (w1 < mv) { mv = w1; am = 1; }
                    if (w2 < mv) { mv = w2; am = 2; }
                    if (w3 < mv) { mv = w3; am = 3; }
                    int nb = topo[4 * tet + (3 - am)];
                    if (nb >= 0) {
                        tet = nb;
                        int4 tv = ((const int4*)tetras)[tet];
                        ca  = ld3(verts + 3 * tv.x);
                        F3 b  = ld3(verts + 3 * tv.y);
                        F3 c  = ld3(verts + 3 * tv.z);
                        F3 dd = ld3(verts + 3 * tv.w);
                        ce1 = sub3(b, ca);
                        ce2 = sub3(c, ca);
                        ce3 = sub3(dd, ca);
                        cc23 = cross3(ce2, ce3);
                        float det = dot3(ce1, cc23);
                        cinv = 1.0f / det;
                        moved_last = true;
                    } else { alive = false; break; }
                }
                if (alive && !inside && moved_last) {
                    F3 r = sub3(p, ca);
                    w1 = dot3(r, cc23) * cinv;
                    F3 cr3 = cross3(r, ce3);
                    w2 = dot3(ce1, cr3) * cinv;
                    F3 c2r = cross3(ce2, r);
                    w3 = dot3(ce1, c2r) * cinv;
                    w0 = 1.0f - (w1 + w2 + w3);
                    inside = (w0 >= -1e-6f) && (w1 >= -1e-6f) &&
                             (w2 >= -1e-6f) && (w3 >= -1e-6f);
                }
                valid = alive && inside;
            }

            int idx = ray * MAXS + k + j;
            if (valid) {
                o_ray[idx] = (float)ray;
                o_tet[idx] = (float)tet;
                ((float4*)o_bar)[idx] = make_float4(w0, w1, w2, w3);
                o_pos[3 * idx + 0] = p.x;
                o_pos[3 * idx + 1] = p.y;
                o_pos[3 * idx + 2] = p.z;
            } else {
                o_ray[idx] = -1.0f;
                o_tet[idx] = -1.0f;
                ((float4*)o_bar)[idx] = make_float4(0.f, 0.f, 0.f, 0.f);
                o_pos[3 * idx + 0] = 0.0f;
                o_pos[3 * idx + 1] = 0.0f;
                o_pos[3 * idx + 2] = 0.0f;
            }
            if (restart) { ++j; break; }
        }
        k += j;
    }

    // tail fill: dead (or never-hit) rays emit invalid samples
    for (int kk = k; kk < MAXS; ++kk) {
        int idx = ray * MAXS + kk;
        o_ray[idx] = -1.0f;
        o_tet[idx] = -1.0f;
        ((float4*)o_bar)[idx] = make_float4(0.f, 0.f, 0.f, 0.f);
        o_pos[3 * idx + 0] = 0.0f;
        o_pos[3 * idx + 1] = 0.0f;
        o_pos[3 * idx + 2] = 0.0f;
    }
}

// ---------------- launch ------------------------------------------------------
extern "C" void kernel_launch(void* const* d_in, const int* in_sizes, int n_in,
                              void* d_out, int out_size) {
    const float* cage   = (const float*)d_in[0];  // (1, 729, 3) f32
    const float* ro     = (const float*)d_in[1];  // (1, 4096, 3) f32
    const float* rd     = (const float*)d_in[2];  // (1, 4096, 3) f32
    const int*   tetras = (const int*)d_in[3];    // (3072, 4) i32
    const int*   faces  = (const int*)d_in[4];    // (3072, 4, 3) i32
    const int*   topo   = (const int*)d_in[5];    // (3072, 4) i32
    float* out = (float*)d_out;

    k_prep<<<1, 256>>>(cage, faces, topo);
    k_isect<<<NRAYS / 32, 256>>>(ro, rd);
    k_march<<<NRAYS / 32, 32>>>(cage, ro, rd, tetras, topo, out);
}

// round 6
// speedup vs baseline: 1.6127x; 1.5807x over previous
#include <cuda_runtime.h>
#include <cuda_bf16.h>

#define NRAYS 4096
#define NTETS 3072
#define NFACE 12288
#define MAXS  128

// ---------------- scratch (device globals; no allocations) ------------------
__device__ float4 g_btri[NFACE * 3];            // boundary tri: p0,e1,e2; fid in [0].w
__device__ int    g_nb;                          // boundary tri count
__device__ unsigned long long g_key[NRAYS];      // packed (t_bits<<32 | face_idx)

struct F3 { float x, y, z; };
__device__ __forceinline__ F3 mkf3(float x, float y, float z) { F3 r; r.x = x; r.y = y; r.z = z; return r; }
__device__ __forceinline__ F3 sub3(F3 a, F3 b) { return mkf3(a.x - b.x, a.y - b.y, a.z - b.z); }
__device__ __forceinline__ F3 cross3(F3 a, F3 b) {
    return mkf3(a.y * b.z - a.z * b.y,
                a.z * b.x - a.x * b.z,
                a.x * b.y - a.y * b.x);
}
__device__ __forceinline__ float dot3(F3 a, F3 b) { return a.x * b.x + a.y * b.y + a.z * b.z; }
__device__ __forceinline__ F3 ld3(const float* p) { return mkf3(p[0], p[1], p[2]); }

// ---------------- kernel 0: reset boundary counter ---------------------------
__global__ void k_reset() { g_nb = 0; }

// ---------------- kernel 1: compact boundary triangles (grid-wide) -----------
// topo flattened (NTETS*4) is indexed exactly by face id; boundary <=> topo<0.
// Slot order is non-deterministic but the isect min-reduction is order-
// independent ((t, fid) tie-break), so results are deterministic.
__global__ void k_prep(const float* __restrict__ verts,
                       const int* __restrict__ faces,
                       const int* __restrict__ topo) {
    int fid = blockIdx.x * blockDim.x + threadIdx.x;
    if (fid >= NFACE) return;
    if (topo[fid] >= 0) return;                 // interior face: cannot be first hit
    int slot = atomicAdd(&g_nb, 1);
    int v0 = faces[3 * fid + 0];
    int v1 = faces[3 * fid + 1];
    int v2 = faces[3 * fid + 2];
    F3 p0 = ld3(verts + 3 * v0);
    F3 p1 = ld3(verts + 3 * v1);
    F3 p2 = ld3(verts + 3 * v2);
    g_btri[3 * slot + 0] = make_float4(p0.x, p0.y, p0.z, __int_as_float(fid));
    g_btri[3 * slot + 1] = make_float4(p1.x - p0.x, p1.y - p0.y, p1.z - p0.z, 0.0f);
    g_btri[3 * slot + 2] = make_float4(p2.x - p0.x, p2.y - p0.y, p2.z - p0.z, 0.0f);
}

// ---------------- kernel 2: intersect, block-reduced -------------------------
// Block = 512 threads = 32 rays x 16 tri-slices; shared atomicMin on packed
// (t_bits<<32 | fid) reproduces first-occurrence argmin; one coalesced g_key
// write per block.
__global__ void __launch_bounds__(512) k_isect(const float* __restrict__ ro,
                                               const float* __restrict__ rd) {
    __shared__ unsigned long long skey[32];
    int tid  = threadIdx.x;
    int lane = tid & 31;
    int wid  = tid >> 5;                 // 0..15 = tri-slice
    int ray  = blockIdx.x * 32 + lane;

    if (tid < 32)
        skey[tid] = ((unsigned long long)__float_as_uint(1e10f) << 32); // (1e10, 0)
    __syncthreads();

    F3 o = ld3(ro + 3 * ray);
    F3 d = ld3(rd + 3 * ray);
    int nb = g_nb;

    float tmin = 1e10f;
    int   fmin = 0x7fffffff;
    for (int s = wid; s < nb; s += 16) {
        float4 q0 = g_btri[3 * s + 0];
        float4 q1 = g_btri[3 * s + 1];
        float4 q2 = g_btri[3 * s + 2];
        F3 p0 = mkf3(q0.x, q0.y, q0.z);
        F3 e1 = mkf3(q1.x, q1.y, q1.z);
        F3 e2 = mkf3(q2.x, q2.y, q2.z);
        int fid = __float_as_int(q0.w);

        F3 h = cross3(d, e2);
        float a = dot3(e1, h);
        bool anz = fabsf(a) > 1e-9f;
        float f = 1.0f / (anz ? a : 1e-9f);
        F3 s3 = sub3(o, p0);
        float u = f * dot3(s3, h);
        F3 q = cross3(s3, e1);
        float v = f * dot3(d, q);
        float tt = f * dot3(e2, q);
        bool ok = anz && (u >= 0.0f) && (u <= 1.0f) && (v >= 0.0f) &&
                  (u + v <= 1.0f) && (tt > 1e-6f);
        if (ok && (tt < tmin || (tt == tmin && fid < fmin))) { tmin = tt; fmin = fid; }
    }
    if (tmin < 1e10f) {
        unsigned long long key =
            ((unsigned long long)__float_as_uint(tmin) << 32) | (unsigned)fmin;
        atomicMin(&skey[lane], key);
    }
    __syncthreads();
    if (tid < 32) g_key[ray] = skey[tid];
}

// ---------------- kernel 3: march with 4-wide speculative batching -----------
// Common case: sample is inside the carried tet at the first bary (reference's
// it=0 path). Compute 4 consecutive samples' bary against the cached tet as
// independent chains; any failure falls into the verbatim R3 walk and restarts
// the batch with the new tet. All arithmetic is op-identical to R3.
__global__ void __launch_bounds__(32) k_march(const float* __restrict__ verts,
                                              const float* __restrict__ ro,
                                              const float* __restrict__ rd,
                                              const int* __restrict__ tetras,
                                              const int* __restrict__ topo,
                                              float* __restrict__ out) {
    int ray = blockIdx.x * 32 + threadIdx.x;

    unsigned long long key = g_key[ray];
    float tmin = __uint_as_float((unsigned)(key >> 32));
    int   fidx = (int)(key & 0xffffffffu);

    bool  hit = tmin < 5.0f;
    float t0  = hit ? tmin : 0.0f;
    F3 o = ld3(ro + 3 * ray);
    F3 d = ld3(rd + 3 * ray);
    F3 hp = mkf3(o.x + t0 * d.x, o.y + t0 * d.y, o.z + t0 * d.z);
    int  tet   = hit ? (fidx >> 2) : 0;
    bool alive = hit;

    float* o_ray = out;
    float* o_tet = out + (size_t)NRAYS * MAXS;
    float* o_bar = out + (size_t)2 * NRAYS * MAXS;
    float* o_ts  = out + (size_t)6 * NRAYS * MAXS;
    float* o_te  = o_ts + NRAYS;
    float* o_pos = o_te + NRAYS;

    o_ts[ray] = t0;
    o_te[ray] = hit ? (t0 + 0.05f) : 0.0f;

    const float STEPF = (float)(0.05 / 128.0);

    // register-cached tet data (identical computation to R3)
    F3 ca, ce1, ce2, ce3, cc23;
    float cinv = 0.0f;
    if (alive) {
        int4 tv = ((const int4*)tetras)[tet];
        ca  = ld3(verts + 3 * tv.x);
        F3 b  = ld3(verts + 3 * tv.y);
        F3 c  = ld3(verts + 3 * tv.z);
        F3 dd = ld3(verts + 3 * tv.w);
        ce1 = sub3(b, ca);
        ce2 = sub3(c, ca);
        ce3 = sub3(dd, ca);
        cc23 = cross3(ce2, ce3);
        float det = dot3(ce1, cc23);
        cinv = 1.0f / det;
    }

    int k = 0;
    while (alive && k < MAXS) {
        int kb = MAXS - k;
        if (kb > 4) kb = 4;

        float W0[4], W1[4], W2[4], W3[4], PXa[4], PYa[4], PZa[4];
#pragma unroll
        for (int j = 0; j < 4; ++j) {
            if (j < kb) {
                float tk = (float)(k + j) * STEPF + 1e-4f;
                F3 p = mkf3(hp.x + tk * d.x, hp.y + tk * d.y, hp.z + tk * d.z);
                F3 r = sub3(p, ca);
                float w1 = dot3(r, cc23) * cinv;
                F3 cr3 = cross3(r, ce3);
                float w2 = dot3(ce1, cr3) * cinv;
                F3 c2r = cross3(ce2, r);
                float w3 = dot3(ce1, c2r) * cinv;
                W1[j] = w1; W2[j] = w2; W3[j] = w3;
                W0[j] = 1.0f - (w1 + w2 + w3);
                PXa[j] = p.x; PYa[j] = p.y; PZa[j] = p.z;
            }
        }

        int j = 0;
        bool restart = false;
        for (; j < kb; ++j) {
            float w0 = W0[j], w1 = W1[j], w2 = W2[j], w3 = W3[j];
            F3 p = mkf3(PXa[j], PYa[j], PZa[j]);
            bool inside = (w0 >= -1e-6f) && (w1 >= -1e-6f) &&
                          (w2 >= -1e-6f) && (w3 >= -1e-6f);
            bool valid;
            if (inside) {
                valid = true;
            } else {
                // slow path: verbatim R3 walk, it=0 bary already in w*
                restart = true;
                bool moved_last = false;
                for (int it = 0; it < 3; ++it) {
                    if (it > 0) {
                        F3 r = sub3(p, ca);
                        w1 = dot3(r, cc23) * cinv;
                        F3 cr3 = cross3(r, ce3);
                        w2 = dot3(ce1, cr3) * cinv;
                        F3 c2r = cross3(ce2, r);
                        w3 = dot3(ce1, c2r) * cinv;
                        w0 = 1.0f - (w1 + w2 + w3);
                        inside = (w0 >= -1e-6f) && (w1 >= -1e-6f) &&
                                 (w2 >= -1e-6f) && (w3 >= -1e-6f);
                    }
                    moved_last = false;
                    if (inside) break;
                    int am = 0; float mv = w0;
                    if (w1 < mv) { mv = w1; am = 1; }
                    if (w2 < mv) { mv = w2; am = 2; }
                    if (w3 < mv) { mv = w3; am = 3; }
                    int nb = topo[4 * tet + (3 - am)];
                    if (nb >= 0) {
                        tet = nb;
                        int4 tv = ((const int4*)tetras)[tet];
                        ca  = ld3(verts + 3 * tv.x);
                        F3 b  = ld3(verts + 3 * tv.y);
                        F3 c  = ld3(verts + 3 * tv.z);
                        F3 dd = ld3(verts + 3 * tv.w);
                        ce1 = sub3(b, ca);
                        ce2 = sub3(c, ca);
                        ce3 = sub3(dd, ca);
                        cc23 = cross3(ce2, ce3);
                        float det = dot3(ce1, cc23);
                        cinv = 1.0f / det;
                        moved_last = true;
                    } else { alive = false; break; }
                }
                if (alive && !inside && moved_last) {
                    F3 r = sub3(p, ca);
                    w1 = dot3(r, cc23) * cinv;
                    F3 cr3 = cross3(r, ce3);
                    w2 = dot3(ce1, cr3) * cinv;
                    F3 c2r = cross3(ce2, r);
                    w3 = dot3(ce1, c2r) * cinv;
                    w0 = 1.0f - (w1 + w2 + w3);
                    inside = (w0 >= -1e-6f) && (w1 >= -1e-6f) &&
                             (w2 >= -1e-6f) && (w3 >= -1e-6f);
                }
                valid = alive && inside;
            }

            int idx = ray * MAXS + k + j;
            if (valid) {
                o_ray[idx] = (float)ray;
                o_tet[idx] = (float)tet;
                ((float4*)o_bar)[idx] = make_float4(w0, w1, w2, w3);
                o_pos[3 * idx + 0] = p.x;
                o_pos[3 * idx + 1] = p.y;
                o_pos[3 * idx + 2] = p.z;
            } else {
                o_ray[idx] = -1.0f;
                o_tet[idx] = -1.0f;
                ((float4*)o_bar)[idx] = make_float4(0.f, 0.f, 0.f, 0.f);
                o_pos[3 * idx + 0] = 0.0f;
                o_pos[3 * idx + 1] = 0.0f;
                o_pos[3 * idx + 2] = 0.0f;
            }
            if (restart) { ++j; break; }
        }
        k += j;
    }

    // tail fill: dead (or never-hit) rays emit invalid samples
    for (int kk = k; kk < MAXS; ++kk) {
        int idx = ray * MAXS + kk;
        o_ray[idx] = -1.0f;
        o_tet[idx] = -1.0f;
        ((float4*)o_bar)[idx] = make_float4(0.f, 0.f, 0.f, 0.f);
        o_pos[3 * idx + 0] = 0.0f;
        o_pos[3 * idx + 1] = 0.0f;
        o_pos[3 * idx + 2] = 0.0f;
    }
}

// ---------------- launch ------------------------------------------------------
extern "C" void kernel_launch(void* const* d_in, const int* in_sizes, int n_in,
                              void* d_out, int out_size) {
    const float* cage   = (const float*)d_in[0];  // (1, 729, 3) f32
    const float* ro     = (const float*)d_in[1];  // (1, 4096, 3) f32
    const float* rd     = (const float*)d_in[2];  // (1, 4096, 3) f32
    const int*   tetras = (const int*)d_in[3];    // (3072, 4) i32
    const int*   faces  = (const int*)d_in[4];    // (3072, 4, 3) i32
    const int*   topo   = (const int*)d_in[5];    // (3072, 4) i32
    float* out = (float*)d_out;

    k_reset<<<1, 1>>>();
    k_prep<<<(NFACE + 255) / 256, 256>>>(cage, faces, topo);
    k_isect<<<NRAYS / 32, 512>>>(ro, rd);
    k_march<<<NRAYS / 32, 32>>>(cage, ro, rd, tetras, topo, out);
}